// round 11
// baseline (speedup 1.0000x reference)
#include <cuda_runtime.h>
#include <cuda_bf16.h>

#define FULLMASK 0xffffffffu

__device__ float g_losses[256];

// One CTA = ONE batch = 128 threads = 4 warps (one per SMSP), occ 2, grid 256.
// Thread owns ONE column c: 64 bf16x2 expT regs, 64 HFMA2/step in 8 chains.
// Tail minimization: exp(feat) software-pipelined 2 steps ahead (off critical
// path), bf16<->f32 via ALU bit ops instead of cvt, 8 short FMA chains.
__global__ void __launch_bounds__(128, 2) k_crf_forward(
    const float* __restrict__ feats,   // [B,S,L]
    const float* __restrict__ startT,  // [L]
    const float* __restrict__ endT,    // [L]
    const float* __restrict__ trans,   // [L,L]
    const float* __restrict__ conf,    // [B]
    const int*   __restrict__ mask,    // [B,S]
    const int*   __restrict__ labels,  // [B,S]
    int S)
{
    constexpr int L = 128;
    extern __shared__ char sm[];
    char*  ebuf  = sm;                             // [2][128] bf16 = 512B
    int*   smask = (int*)(sm + 512);               // [S]
    float* sred  = (float*)(sm + 512 + S * 4);     // [8]

    const int c   = threadIdx.x;       // owned column
    const int wid = c >> 5;            // warp 0..3
    const int b   = blockIdx.x;

    const float* fb = feats + (size_t)b * S * L;

    // ---- expT column c into registers: 64 bf16x2 (i-pairs) ----
    __nv_bfloat162 T[64];
    #pragma unroll
    for (int k = 0; k < 64; ++k) {
        float t0 = __expf(__ldg(trans + (size_t)(2 * k) * L + c));
        float t1 = __expf(__ldg(trans + (size_t)(2 * k + 1) * L + c));
        T[k] = __floats2bfloat162_rn(t0, t1);
    }
    for (int k = c; k < S; k += 128) smask[k] = mask[b * S + k];

    // ---- alpha0 ----
    float a0 = startT[c] + fb[c];
    __syncthreads();                       // smask ready
    float mv = a0;
    #pragma unroll
    for (int o = 16; o; o >>= 1) mv = fmaxf(mv, __shfl_xor_sync(FULLMASK, mv, o));
    if ((c & 31) == 0) sred[wid] = mv;
    __syncthreads();
    float m0 = fmaxf(fmaxf(sred[0], sred[1]), fmaxf(sred[2], sred[3]));

    float v = __expf(a0 - m0);             // exp-domain alpha, normalized
    float offset = m0;                     // alpha = offset + log(v)
    *(__nv_bfloat16*)(ebuf + 256 + 2 * c) = __float2bfloat16(v);  // phase 1

    // exp(feat) pipeline: eCurNext = exp(feat_{t}) ready at step t.
    float e1   = __expf(fb[L + c]);                          // exp(feat_1)
    float raw1 = (S > 2) ? fb[2 * (size_t)L + c] : 0.f;      // feat_2 raw
    float raw2 = (S > 3) ? fb[3 * (size_t)L + c] : 0.f;      // feat_3 raw
    __syncthreads();

    const __nv_bfloat162 bz = __floats2bfloat162_rn(0.f, 0.f);

    for (int t = 1; t < S; ++t) {
        const uint4* se = (const uint4*)(ebuf + (t & 1) * 256);   // read phase
        char*        wb = ebuf + ((t & 1) ^ 1) * 256;             // write phase

        __nv_bfloat162 acc[8];
        #pragma unroll
        for (int i = 0; i < 8; ++i) acc[i] = bz;

        unsigned e0bits = 0;
        #pragma unroll
        for (int p = 0; p < 16; ++p) {
            uint4 q = se[p];                       // e[8p .. 8p+7]
            if (p == 0) e0bits = q.x;              // e[0] in low bf16
            acc[(4 * p + 0) & 7] = __hfma2(*(__nv_bfloat162*)&q.x, T[4 * p + 0], acc[(4 * p + 0) & 7]);
            acc[(4 * p + 1) & 7] = __hfma2(*(__nv_bfloat162*)&q.y, T[4 * p + 1], acc[(4 * p + 1) & 7]);
            acc[(4 * p + 2) & 7] = __hfma2(*(__nv_bfloat162*)&q.z, T[4 * p + 2], acc[(4 * p + 2) & 7]);
            acc[(4 * p + 3) & 7] = __hfma2(*(__nv_bfloat162*)&q.w, T[4 * p + 3], acc[(4 * p + 3) & 7]);
        }
        // rescale factor path (runs during FMA phase, off the tail)
        float e0f = __uint_as_float(e0bits << 16);            // exact bf16->f32

        acc[0] = __hadd2(acc[0], acc[1]);
        acc[2] = __hadd2(acc[2], acc[3]);
        acc[4] = __hadd2(acc[4], acc[5]);
        acc[6] = __hadd2(acc[6], acc[7]);
        acc[0] = __hadd2(acc[0], acc[2]);
        acc[4] = __hadd2(acc[4], acc[6]);
        acc[0] = __hadd2(acc[0], acc[4]);
        unsigned pb = *(unsigned*)&acc[0];
        float slo = __uint_as_float(pb << 16);                // exact widen
        float shi = __uint_as_float(pb & 0xffff0000u);
        float s = slo + shi;

        // advance exp pipeline (independent of the dot)
        float eCur = e1;                      // exp(feat_t), ready
        e1 = __expf(raw1);                    // exp(feat_{t+1}); raw1 aged 2 steps
        raw1 = raw2;
        if (t + 3 < S) raw2 = fb[(size_t)(t + 3) * L + c];

        if (smask[t]) {
            float mfac = eCur;
            if ((t & 3) == 0) {               // uniform rescale by e[0]
                mfac *= __frcp_rn(e0f);
                offset += __logf(e0f);
            }
            v = s * mfac;
        }
        // else masked: alpha (v) carries over unchanged

        unsigned vb = __float_as_uint(v) + 0x8000u;           // round-to-nearest
        *(unsigned short*)(wb + 2 * c) = (unsigned short)(vb >> 16);
        __syncthreads();
    }

    // ---- denominator ----
    float contrib = v * __expf(endT[c]);
    #pragma unroll
    for (int o = 16; o; o >>= 1) contrib += __shfl_xor_sync(FULLMASK, contrib, o);
    if ((c & 31) == 0) sred[wid] = contrib;
    __syncthreads();
    float log_den = offset + __logf((sred[0] + sred[1]) + (sred[2] + sred[3]));
    __syncthreads();

    // ---- numerator: label-path score (exact fp32) ----
    float num = 0.f;
    float slf = 0.f;
    const int* lb = labels + b * S;
    for (int k = c; k < S; k += 128) {
        int mk = smask[k];
        slf += (float)mk;
        int lab = lb[k]; if (lab == -100) lab = 0;
        if (k == 0) {
            num += startT[lab] + fb[lab];
        } else if (mk) {
            int lp = lb[k - 1]; if (lp == -100) lp = 0;
            num += trans[lp * L + lab] + fb[(size_t)k * L + lab];
        }
    }
    #pragma unroll
    for (int o = 16; o; o >>= 1) {
        num += __shfl_xor_sync(FULLMASK, num, o);
        slf += __shfl_xor_sync(FULLMASK, slf, o);
    }
    if ((c & 31) == 0) { sred[wid] = num; sred[4 + wid] = slf; }
    __syncthreads();
    num = (sred[0] + sred[1]) + (sred[2] + sred[3]);
    slf = (sred[4] + sred[5]) + (sred[6] + sred[7]);

    int lastt = (int)(slf + 0.5f) - 1;
    if (lastt < 0) lastt = 0;
    int lastlab = lb[lastt]; if (lastlab == -100) lastlab = 0;
    num += endT[lastlab];

    if (c == 0) g_losses[b] = (log_den - num) * conf[b];
}

__global__ void k_finalize(float* __restrict__ out, int B) {
    int t = threadIdx.x;
    float x = (t < B) ? g_losses[t] : 0.f;
    #pragma unroll
    for (int o = 16; o; o >>= 1) x += __shfl_xor_sync(FULLMASK, x, o);
    __shared__ float sh[8];
    if ((t & 31) == 0) sh[t >> 5] = x;
    __syncthreads();
    if (t == 0) {
        float s = 0.f;
        int nw = (blockDim.x + 31) >> 5;
        for (int w = 0; w < nw; ++w) s += sh[w];
        out[0] = s / (float)B;
    }
}

extern "C" void kernel_launch(void* const* d_in, const int* in_sizes, int n_in,
                              void* d_out, int out_size) {
    const float* feats  = (const float*)d_in[0];
    const float* startT = (const float*)d_in[1];
    const float* endT   = (const float*)d_in[2];
    const float* trans  = (const float*)d_in[3];
    const float* conf   = (const float*)d_in[4];
    const int*   mask   = (const int*)  d_in[5];
    const int*   labels = (const int*)  d_in[6];

    const int B = in_sizes[4];            // 256
    const int S = in_sizes[5] / B;        // 512
    (void)n_in; (void)out_size;

    size_t smem = 512                     // double-buffered bf16 e vector
                + (size_t)S * 4           // mask
                + 32;                     // reduction scratch

    k_crf_forward<<<B, 128, smem>>>(feats, startT, endT, trans, conf,
                                    mask, labels, S);
    k_finalize<<<1, 256>>>((float*)d_out, B);
}